// round 1
// baseline (speedup 1.0000x reference)
#include <cuda_runtime.h>
#include <math.h>

// Problem constants (fixed shapes for SDPAWrapper_2216203124921)
#define H_  16
#define S_  4096
#define D_  128
#define BM  64
#define BN  64
#define NT  256
#define SPAD 129   // D_ + 1 : odd float stride -> conflict-free row-strided LDS
#define PPAD 65    // BN + 1

__global__ __launch_bounds__(NT, 1)
void fa_block_causal(const float* __restrict__ q,
                     const float* __restrict__ k,
                     const float* __restrict__ v,
                     const void*  __restrict__ cu_raw,
                     float* __restrict__ out)
{
    extern __shared__ float smem[];
    float* Qs    = smem;                    // BM * SPAD
    float* Ks    = Qs + BM * SPAD;          // BN * SPAD
    float* Vs    = Ks + BN * SPAD;          // BN * SPAD
    float* Ps    = Vs + BN * SPAD;          // BM * PPAD
    float* row_m = Ps + BM * PPAD;          // BM
    float* row_l = row_m + BM;              // BM
    int*   row_st = (int*)(row_l + BM);     // BM
    int*   cu_s   = row_st + BM;            // 9

    const int tid = threadIdx.x;
    const int m0  = blockIdx.x * BM;
    const int h   = blockIdx.y;

    // --- cu_seqlens load with dtype sniff (cu[0]==0 always; int64 => first 8 bytes == 0) ---
    if (tid == 0) {
        long long first = *(const long long*)cu_raw;
        if (first == 0) {
            const long long* c = (const long long*)cu_raw;
            #pragma unroll
            for (int i = 0; i < 9; i++) cu_s[i] = (int)c[i];
        } else {
            const int* c = (const int*)cu_raw;
            #pragma unroll
            for (int i = 0; i < 9; i++) cu_s[i] = c[i];
        }
    }
    if (tid < BM) { row_m[tid] = -INFINITY; row_l[tid] = 0.f; }
    __syncthreads();

    // per-row document start (monotone non-decreasing in q)
    if (tid < BM) {
        int qpos = m0 + tid;
        int st = 0;
        #pragma unroll
        for (int i = 1; i < 9; i++) if (cu_s[i] <= qpos) st = cu_s[i];
        row_st[tid] = st;
    }

    // --- load Q tile (pre-scaled by 1/sqrt(D)) ---
    const float scale = 0.08838834764831843f; // 1/sqrt(128)
    const float* qb = q + ((size_t)h * S_ + m0) * D_;
    for (int i = tid; i < BM * (D_ / 4); i += NT) {
        int r = i >> 5;           // D_/4 == 32
        int c = (i & 31) << 2;
        float4 t = *(const float4*)(qb + r * D_ + c);
        Qs[r * SPAD + c + 0] = t.x * scale;
        Qs[r * SPAD + c + 1] = t.y * scale;
        Qs[r * SPAD + c + 2] = t.z * scale;
        Qs[r * SPAD + c + 3] = t.w * scale;
    }
    __syncthreads();

    const int n_begin = (row_st[0] / BN) * BN;  // earliest doc start in this block
    const int n_end   = m0 + BM;                // causal upper bound (exclusive)

    const int ty = tid >> 4;  // 0..15 : S-rows ty*4 + i
    const int tx = tid & 15;  // 0..15 : S-cols tx + 16*j ; O-cols tx + 16*jj

    float o[4][8];
    #pragma unroll
    for (int i = 0; i < 4; i++)
        #pragma unroll
        for (int jj = 0; jj < 8; jj++) o[i][jj] = 0.f;

    for (int n0 = n_begin; n0 < n_end; n0 += BN) {
        // --- load K, V tiles ---
        const float* kb = k + ((size_t)h * S_ + n0) * D_;
        const float* vb = v + ((size_t)h * S_ + n0) * D_;
        for (int i = tid; i < BN * (D_ / 4); i += NT) {
            int r = i >> 5;
            int c = (i & 31) << 2;
            float4 tk = *(const float4*)(kb + r * D_ + c);
            Ks[r * SPAD + c + 0] = tk.x;
            Ks[r * SPAD + c + 1] = tk.y;
            Ks[r * SPAD + c + 2] = tk.z;
            Ks[r * SPAD + c + 3] = tk.w;
            float4 tv = *(const float4*)(vb + r * D_ + c);
            Vs[r * SPAD + c + 0] = tv.x;
            Vs[r * SPAD + c + 1] = tv.y;
            Vs[r * SPAD + c + 2] = tv.z;
            Vs[r * SPAD + c + 3] = tv.w;
        }
        __syncthreads();

        // --- S = Qs @ Ks^T (4x4 micro-tile per thread) ---
        float s[4][4];
        #pragma unroll
        for (int i = 0; i < 4; i++)
            #pragma unroll
            for (int j = 0; j < 4; j++) s[i][j] = 0.f;

        #pragma unroll 4
        for (int kd = 0; kd < D_; kd++) {
            float a0 = Qs[(ty * 4 + 0) * SPAD + kd];
            float a1 = Qs[(ty * 4 + 1) * SPAD + kd];
            float a2 = Qs[(ty * 4 + 2) * SPAD + kd];
            float a3 = Qs[(ty * 4 + 3) * SPAD + kd];
            float b0 = Ks[(tx +  0) * SPAD + kd];
            float b1 = Ks[(tx + 16) * SPAD + kd];
            float b2 = Ks[(tx + 32) * SPAD + kd];
            float b3 = Ks[(tx + 48) * SPAD + kd];
            s[0][0] += a0 * b0; s[0][1] += a0 * b1; s[0][2] += a0 * b2; s[0][3] += a0 * b3;
            s[1][0] += a1 * b0; s[1][1] += a1 * b1; s[1][2] += a1 * b2; s[1][3] += a1 * b3;
            s[2][0] += a2 * b0; s[2][1] += a2 * b1; s[2][2] += a2 * b2; s[2][3] += a2 * b3;
            s[3][0] += a3 * b0; s[3][1] += a3 * b1; s[3][2] += a3 * b2; s[3][3] += a3 * b3;
        }

        // --- mask + online softmax (row groups of 16 lanes share a row) ---
        #pragma unroll
        for (int i = 0; i < 4; i++) {
            const int r    = ty * 4 + i;
            const int qpos = m0 + r;
            const int st   = row_st[r];
            float tmax = -INFINITY;
            #pragma unroll
            for (int j = 0; j < 4; j++) {
                int kpos = n0 + tx + 16 * j;
                if (kpos > qpos || kpos < st) s[i][j] = -INFINITY;
                tmax = fmaxf(tmax, s[i][j]);
            }
            #pragma unroll
            for (int off = 8; off >= 1; off >>= 1)
                tmax = fmaxf(tmax, __shfl_xor_sync(0xffffffffu, tmax, off));

            float mold = row_m[r];
            float mnew = fmaxf(mold, tmax);
            float alpha = (mnew == -INFINITY) ? 1.f : __expf(mold - mnew);

            float lsum = 0.f;
            #pragma unroll
            for (int j = 0; j < 4; j++) {
                float p = (s[i][j] == -INFINITY) ? 0.f : __expf(s[i][j] - mnew);
                s[i][j] = p;
                lsum += p;
            }
            #pragma unroll
            for (int off = 8; off >= 1; off >>= 1)
                lsum += __shfl_xor_sync(0xffffffffu, lsum, off);

            #pragma unroll
            for (int jj = 0; jj < 8; jj++) o[i][jj] *= alpha;

            if (tx == 0) { row_m[r] = mnew; row_l[r] = alpha * row_l[r] + lsum; }

            #pragma unroll
            for (int j = 0; j < 4; j++) Ps[r * PPAD + tx + 16 * j] = s[i][j];
        }
        __syncthreads();

        // --- O += P @ V (4x8 micro-tile per thread) ---
        #pragma unroll 2
        for (int kk = 0; kk < BN; kk++) {
            float a0 = Ps[(ty * 4 + 0) * PPAD + kk];
            float a1 = Ps[(ty * 4 + 1) * PPAD + kk];
            float a2 = Ps[(ty * 4 + 2) * PPAD + kk];
            float a3 = Ps[(ty * 4 + 3) * PPAD + kk];
            #pragma unroll
            for (int jj = 0; jj < 8; jj++) {
                float b = Vs[kk * SPAD + tx + 16 * jj];
                o[0][jj] += a0 * b;
                o[1][jj] += a1 * b;
                o[2][jj] += a2 * b;
                o[3][jj] += a3 * b;
            }
        }
        __syncthreads();  // protect Ks/Vs/Ps for next iteration
    }

    // --- epilogue: normalize and store ---
    float* ob = out + ((size_t)h * S_ + m0) * D_;
    #pragma unroll
    for (int i = 0; i < 4; i++) {
        int r = ty * 4 + i;
        float inv = 1.f / row_l[r];
        #pragma unroll
        for (int jj = 0; jj < 8; jj++)
            ob[r * D_ + tx + 16 * jj] = o[i][jj] * inv;
    }
}

extern "C" void kernel_launch(void* const* d_in, const int* in_sizes, int n_in,
                              void* d_out, int out_size)
{
    const float* q  = (const float*)d_in[0];
    const float* k  = (const float*)d_in[1];
    const float* v  = (const float*)d_in[2];
    const void*  cu = d_in[3];
    float* out = (float*)d_out;

    const int smem_bytes = (BM * SPAD * 3 + BM * PPAD + 2 * BM) * (int)sizeof(float)
                         + (BM + 9) * (int)sizeof(int);

    static int configured = 0;
    if (!configured) {
        cudaFuncSetAttribute(fa_block_causal,
                             cudaFuncAttributeMaxDynamicSharedMemorySize, smem_bytes);
        configured = 1;
    }

    dim3 grid(S_ / BM, H_);
    fa_block_causal<<<grid, NT, smem_bytes>>>(q, k, v, cu, out);
}

// round 5
// speedup vs baseline: 1.8802x; 1.8802x over previous
#include <cuda_runtime.h>
#include <cuda_bf16.h>
#include <cstdint>

#define H_  16
#define S_  4096
#define D_  128
#define BM  128
#define BN  64
#define NTH 256

// row strides (32-bit words): K,Q = 68 (64 data + 4 pad), V = 36 (32 data + 4 pad)
// 68 mod 32 == 4 and 36 mod 32 == 4 => fragment LDS bank = (4g+t), conflict-free.
#define SK 68
#define SQ 68
#define SV 36

// smem byte offsets
#define KHI 0
#define KLO 17408
#define VHI 34816
#define VLO 53248
#define QHI 71680
#define QLO 106496
#define SMEM_BYTES 141312

static __device__ __forceinline__ float ex2f(float x) {
    float y; asm("ex2.approx.f32 %0, %1;" : "=f"(y) : "f"(x)); return y;
}
// split float pair (x,y) -> packed bf16x2 hi (x in low half) and residual lo
static __device__ __forceinline__ void split2(float x, float y, uint32_t& hi, uint32_t& lo) {
    asm("cvt.rn.bf16x2.f32 %0, %1, %2;" : "=r"(hi) : "f"(y), "f"(x));
    float xr = x - __uint_as_float(hi << 16);
    float yr = y - __uint_as_float(hi & 0xffff0000u);
    asm("cvt.rn.bf16x2.f32 %0, %1, %2;" : "=r"(lo) : "f"(yr), "f"(xr));
}
static __device__ __forceinline__ void split1(float x, uint16_t& h, uint16_t& l) {
    __nv_bfloat16 bh = __float2bfloat16(x);
    __nv_bfloat16 bl = __float2bfloat16(x - __bfloat162float(bh));
    h = *(uint16_t*)&bh; l = *(uint16_t*)&bl;
}
static __device__ __forceinline__ void mma16816(float* c, const uint32_t* a, uint32_t b0, uint32_t b1) {
    asm volatile("mma.sync.aligned.m16n8k16.row.col.f32.bf16.bf16.f32 "
        "{%0,%1,%2,%3}, {%4,%5,%6,%7}, {%8,%9}, {%0,%1,%2,%3};"
        : "+f"(c[0]), "+f"(c[1]), "+f"(c[2]), "+f"(c[3])
        : "r"(a[0]), "r"(a[1]), "r"(a[2]), "r"(a[3]), "r"(b0), "r"(b1));
}

__global__ __launch_bounds__(NTH, 1)
void fa_mma_split(const float* __restrict__ q, const float* __restrict__ k,
                  const float* __restrict__ v, const void* __restrict__ cu_raw,
                  float* __restrict__ out)
{
    extern __shared__ char sm[];
    __shared__ int cu_s[9];
    __shared__ int row_st[BM];

    uint32_t* Khi = (uint32_t*)(sm + KHI);
    uint32_t* Klo = (uint32_t*)(sm + KLO);
    uint16_t* Vhi = (uint16_t*)(sm + VHI);
    uint16_t* Vlo = (uint16_t*)(sm + VLO);
    uint32_t* Qhi = (uint32_t*)(sm + QHI);
    uint32_t* Qlo = (uint32_t*)(sm + QLO);

    const int tid  = threadIdx.x;
    const int w    = tid >> 5;
    const int lane = tid & 31;
    const int g    = lane >> 2;
    const int t    = lane & 3;

    const int m0 = (int)(gridDim.x - 1 - blockIdx.x) * BM;  // longest work first
    const int h  = blockIdx.y;

    if (tid == 0) {
        long long first8 = *(const long long*)cu_raw;  // cu[0]==0; int64 => 8 zero bytes
        if (first8 == 0) {
            const long long* c = (const long long*)cu_raw;
            #pragma unroll
            for (int i = 0; i < 9; i++) cu_s[i] = (int)c[i];
        } else {
            const int* c = (const int*)cu_raw;
            #pragma unroll
            for (int i = 0; i < 9; i++) cu_s[i] = c[i];
        }
    }
    __syncthreads();
    if (tid < BM) {
        int qpos = m0 + tid, st = 0;
        #pragma unroll
        for (int i = 1; i < 9; i++) if (cu_s[i] <= qpos) st = cu_s[i];
        row_st[tid] = st;
    }

    // ---- stage Q packed hi/lo (scaled by 1/sqrt(D)*log2(e) for base-2 softmax) ----
    const float QSC = 0.12752551286084110f;
    {
        const float4* qg = (const float4*)(q + ((size_t)h * S_ + m0) * D_);
        #pragma unroll
        for (int it = 0; it < 16; it++) {
            int idx = it * NTH + tid;
            int row = idx >> 5, c4 = idx & 31;
            float4 tq = qg[idx];
            uint32_t h01, l01, h23, l23;
            split2(tq.x * QSC, tq.y * QSC, h01, l01);
            split2(tq.z * QSC, tq.w * QSC, h23, l23);
            int wo = row * SQ + c4 * 2;
            *(uint2*)(Qhi + wo) = make_uint2(h01, h23);
            *(uint2*)(Qlo + wo) = make_uint2(l01, l23);
        }
    }
    __syncthreads();   // row_st visible to all warps; Q staged

    const int wr    = m0 + w * 16;
    const int r0g   = wr + g, r1g = r0g + 8;
    const int st0   = row_st[w * 16 + g];
    const int st1   = row_st[w * 16 + g + 8];
    const int stmin = row_st[w * 16];
    const int n_begin = (row_st[0] / BN) * BN;
    const int n_end   = m0 + BM;

    float o[16][4];
    #pragma unroll
    for (int i = 0; i < 16; i++) { o[i][0]=0.f; o[i][1]=0.f; o[i][2]=0.f; o[i][3]=0.f; }
    float m0r = -1e30f, m1r = -1e30f, l0 = 0.f, l1 = 0.f;

    for (int n0 = n_begin; n0 < n_end; n0 += BN) {
        // ---- stage K packed hi/lo + V transposed halves ----
        {
            const float4* kg = (const float4*)(k + ((size_t)h * S_ + n0) * D_);
            #pragma unroll
            for (int it = 0; it < 8; it++) {
                int idx = it * NTH + tid;
                int row = idx >> 5, c4 = idx & 31;
                float4 tk = kg[idx];
                uint32_t h01, l01, h23, l23;
                split2(tk.x, tk.y, h01, l01);
                split2(tk.z, tk.w, h23, l23);
                int wo = row * SK + c4 * 2;
                *(uint2*)(Khi + wo) = make_uint2(h01, h23);
                *(uint2*)(Klo + wo) = make_uint2(l01, l23);
            }
            const float4* vg = (const float4*)(v + ((size_t)h * S_ + n0) * D_);
            #pragma unroll
            for (int it = 0; it < 8; it++) {
                int idx = it * NTH + tid;
                int kv = idx >> 5, c4 = idx & 31;
                float4 tv = vg[idx];
                int d0 = c4 * 4;
                uint16_t hh, ll;
                split1(tv.x, hh, ll); Vhi[(d0+0)*(2*SV) + kv] = hh; Vlo[(d0+0)*(2*SV) + kv] = ll;
                split1(tv.y, hh, ll); Vhi[(d0+1)*(2*SV) + kv] = hh; Vlo[(d0+1)*(2*SV) + kv] = ll;
                split1(tv.z, hh, ll); Vhi[(d0+2)*(2*SV) + kv] = hh; Vlo[(d0+2)*(2*SV) + kv] = ll;
                split1(tv.w, hh, ll); Vhi[(d0+3)*(2*SV) + kv] = hh; Vlo[(d0+3)*(2*SV) + kv] = ll;
            }
        }
        __syncthreads();

        if (!(n0 > wr + 15 || n0 + BN - 1 < stmin)) {
            // ---- S = Q K^T (3 split terms) ----
            float s[8][4];
            #pragma unroll
            for (int nt = 0; nt < 8; nt++) { s[nt][0]=0.f; s[nt][1]=0.f; s[nt][2]=0.f; s[nt][3]=0.f; }
            #pragma unroll
            for (int kc = 0; kc < 8; kc++) {
                uint32_t qh[4], ql[4];
                int a0 = (w*16 + g) * SQ + kc*8 + t;
                int a1 = a0 + 8*SQ;
                qh[0]=Qhi[a0]; qh[1]=Qhi[a1]; qh[2]=Qhi[a0+4]; qh[3]=Qhi[a1+4];
                ql[0]=Qlo[a0]; ql[1]=Qlo[a1]; ql[2]=Qlo[a0+4]; ql[3]=Qlo[a1+4];
                #pragma unroll
                for (int nt = 0; nt < 8; nt++) {
                    int b = (nt*8 + g) * SK + kc*8 + t;
                    uint32_t bh0 = Khi[b], bh1 = Khi[b+4];
                    uint32_t bl0 = Klo[b], bl1 = Klo[b+4];
                    mma16816(s[nt], qh, bh0, bh1);
                    mma16816(s[nt], qh, bl0, bl1);
                    mma16816(s[nt], ql, bh0, bh1);
                }
            }

            // ---- mask + online softmax (base-2) ----
            float mx0 = -1e30f, mx1 = -1e30f;
            #pragma unroll
            for (int nt = 0; nt < 8; nt++) {
                int c0 = n0 + nt*8 + 2*t, c1 = c0 + 1;
                if (c0 < st0 || c0 > r0g) s[nt][0] = -1e30f;
                if (c1 < st0 || c1 > r0g) s[nt][1] = -1e30f;
                if (c0 < st1 || c0 > r1g) s[nt][2] = -1e30f;
                if (c1 < st1 || c1 > r1g) s[nt][3] = -1e30f;
                mx0 = fmaxf(mx0, fmaxf(s[nt][0], s[nt][1]));
                mx1 = fmaxf(mx1, fmaxf(s[nt][2], s[nt][3]));
            }
            mx0 = fmaxf(mx0, __shfl_xor_sync(0xffffffffu, mx0, 1));
            mx0 = fmaxf(mx0, __shfl_xor_sync(0xffffffffu, mx0, 2));
            mx1 = fmaxf(mx1, __shfl_xor_sync(0xffffffffu, mx1, 1));
            mx1 = fmaxf(mx1, __shfl_xor_sync(0xffffffffu, mx1, 2));

            float mn0 = fmaxf(m0r, mx0), mn1 = fmaxf(m1r, mx1);
            float ga0 = (mn0 > -1e29f) ? 1.f : 0.f;
            float ga1 = (mn1 > -1e29f) ? 1.f : 0.f;
            float al0 = ex2f(m0r - mn0), al1 = ex2f(m1r - mn1);
            m0r = mn0; m1r = mn1;

            uint32_t ph[8], ph2[8], pl[8], pl2[8];
            float sum0 = 0.f, sum1 = 0.f;
            #pragma unroll
            for (int nt = 0; nt < 8; nt++) {
                float p0 = ex2f(s[nt][0] - mn0) * ga0;
                float p1 = ex2f(s[nt][1] - mn0) * ga0;
                float p2 = ex2f(s[nt][2] - mn1) * ga1;
                float p3 = ex2f(s[nt][3] - mn1) * ga1;
                sum0 += p0 + p1; sum1 += p2 + p3;
                split2(p0, p1, ph[nt],  pl[nt]);
                split2(p2, p3, ph2[nt], pl2[nt]);
            }
            sum0 += __shfl_xor_sync(0xffffffffu, sum0, 1);
            sum0 += __shfl_xor_sync(0xffffffffu, sum0, 2);
            sum1 += __shfl_xor_sync(0xffffffffu, sum1, 1);
            sum1 += __shfl_xor_sync(0xffffffffu, sum1, 2);
            l0 = al0 * l0 + sum0;
            l1 = al1 * l1 + sum1;

            #pragma unroll
            for (int i = 0; i < 16; i++) {
                o[i][0] *= al0; o[i][1] *= al0; o[i][2] *= al1; o[i][3] *= al1;
            }

            // ---- O += P Vt^T (3 split terms) ----
            #pragma unroll
            for (int kc = 0; kc < 4; kc++) {
                uint32_t Ah[4] = { ph[2*kc], ph2[2*kc], ph[2*kc+1], ph2[2*kc+1] };
                uint32_t Al[4] = { pl[2*kc], pl2[2*kc], pl[2*kc+1], pl2[2*kc+1] };
                #pragma unroll
                for (int ntv = 0; ntv < 16; ntv++) {
                    int b = (ntv*8 + g) * SV + kc*8 + t;
                    uint32_t bh0 = ((uint32_t*)Vhi)[b], bh1 = ((uint32_t*)Vhi)[b+4];
                    uint32_t bl0 = ((uint32_t*)Vlo)[b], bl1 = ((uint32_t*)Vlo)[b+4];
                    mma16816(o[ntv], Ah, bh0, bh1);
                    mma16816(o[ntv], Ah, bl0, bl1);
                    mma16816(o[ntv], Al, bh0, bh1);
                }
            }
        }
        __syncthreads();   // compute done before next tile overwrites K/V
    }

    // ---- epilogue ----
    float inv0 = 1.f / l0, inv1 = 1.f / l1;
    float* ob0 = out + ((size_t)h * S_ + r0g) * D_;
    float* ob1 = out + ((size_t)h * S_ + r1g) * D_;
    #pragma unroll
    for (int ntv = 0; ntv < 16; ntv++) {
        int d = ntv * 8 + 2 * t;
        *(float2*)(ob0 + d) = make_float2(o[ntv][0] * inv0, o[ntv][1] * inv0);
        *(float2*)(ob1 + d) = make_float2(o[ntv][2] * inv1, o[ntv][3] * inv1);
    }
}

extern "C" void kernel_launch(void* const* d_in, const int* in_sizes, int n_in,
                              void* d_out, int out_size)
{
    const float* q  = (const float*)d_in[0];
    const float* k  = (const float*)d_in[1];
    const float* v  = (const float*)d_in[2];
    const void*  cu = d_in[3];
    float* out = (float*)d_out;

    static int configured = 0;
    if (!configured) {
        cudaFuncSetAttribute(fa_mma_split,
                             cudaFuncAttributeMaxDynamicSharedMemorySize, SMEM_BYTES);
        configured = 1;
    }
    dim3 grid(S_ / BM, H_);
    fa_mma_split<<<grid, NTH, SMEM_BYTES>>>(q, k, v, cu, out);
}